// round 2
// baseline (speedup 1.0000x reference)
#include <cuda_runtime.h>

#define B_    32
#define C_    256
#define HW    4096
#define NROWS (B_ * C_)
#define NH    5
#define LD    10
#define PROJ  50

__device__ float g_Pq[NROWS * PROJ];
__device__ float g_Pk[NROWS * PROJ];
__device__ float g_Pv[NROWS * PROJ];
__device__ float g_Va2[NROWS * PROJ];
__device__ float g_scale[C_];
__device__ float g_shift[C_];

// ---- packed f32x2 helpers (Blackwell FFMA2) ----
__device__ __forceinline__ unsigned long long pack_dup(float x) {
    unsigned long long r; unsigned u = __float_as_uint(x);
    asm("mov.b64 %0, {%1, %1};" : "=l"(r) : "r"(u));
    return r;
}
__device__ __forceinline__ void fma2(unsigned long long &acc,
                                     unsigned long long a, unsigned long long b) {
    asm("fma.rn.f32x2 %0, %1, %2, %0;" : "+l"(acc) : "l"(a), "l"(b));
}
__device__ __forceinline__ float2 unpack2(unsigned long long p) {
    unsigned lo, hi;
    asm("mov.b64 {%0, %1}, %2;" : "=r"(lo), "=r"(hi) : "l"(p));
    return make_float2(__uint_as_float(lo), __uint_as_float(hi));
}

// ================= kernel 1: projections  P = A @ W  (8192x4096x50) =======
#define TM 64
#define TK 32
__global__ __launch_bounds__(128) void proj_kernel(
    const float* __restrict__ q, const float* __restrict__ k,
    const float* __restrict__ v, const float* __restrict__ wq,
    const float* __restrict__ wk, const float* __restrict__ wv)
{
    __shared__ __align__(16) float As[TK][TM + 4];
    __shared__ __align__(16) float Ws[TK][68];

    const int spec = blockIdx.y;
    const float* A  = (spec == 0) ? q  : (spec == 1) ? k  : v;
    const float* W  = (spec == 0) ? wq : (spec == 1) ? wk : wv;
    float*      Out = (spec == 0) ? g_Pq : (spec == 1) ? g_Pk : g_Pv;

    const int row0 = blockIdx.x * TM;
    const int tid  = threadIdx.x;
    const int rt   = tid >> 3;   // 16 groups of 4 rows
    const int ct   = tid & 7;    // 8 groups of 8 cols

    for (int i = tid; i < TK * 68; i += 128) (&Ws[0][0])[i] = 0.f;

    unsigned long long acc[4][4];
#pragma unroll
    for (int r = 0; r < 4; r++)
#pragma unroll
        for (int cp = 0; cp < 4; cp++) acc[r][cp] = 0ull;

    for (int kt = 0; kt < HW / TK; kt++) {
        const int k0 = kt * TK;
#pragma unroll
        for (int it = 0; it < 4; it++) {
            int i = tid + it * 128;
            int r = i >> 3, kg = i & 7;
            float4 av = *(const float4*)(A + (size_t)(row0 + r) * HW + k0 + kg * 4);
            As[kg * 4 + 0][r] = av.x; As[kg * 4 + 1][r] = av.y;
            As[kg * 4 + 2][r] = av.z; As[kg * 4 + 3][r] = av.w;
        }
        for (int i = tid; i < TK * PROJ; i += 128) {
            int kk = i / PROJ, n = i - kk * PROJ;
            Ws[kk][n] = W[(size_t)(k0 + kk) * PROJ + n];
        }
        __syncthreads();
#pragma unroll
        for (int kk = 0; kk < TK; kk++) {
            const float4 a = *(const float4*)&As[kk][rt * 4];
            const ulonglong2 wA = *(const ulonglong2*)&Ws[kk][ct * 8];
            const ulonglong2 wB = *(const ulonglong2*)&Ws[kk][ct * 8 + 4];
            unsigned long long d0 = pack_dup(a.x), d1 = pack_dup(a.y);
            unsigned long long d2 = pack_dup(a.z), d3 = pack_dup(a.w);
            fma2(acc[0][0], d0, wA.x); fma2(acc[0][1], d0, wA.y);
            fma2(acc[0][2], d0, wB.x); fma2(acc[0][3], d0, wB.y);
            fma2(acc[1][0], d1, wA.x); fma2(acc[1][1], d1, wA.y);
            fma2(acc[1][2], d1, wB.x); fma2(acc[1][3], d1, wB.y);
            fma2(acc[2][0], d2, wA.x); fma2(acc[2][1], d2, wA.y);
            fma2(acc[2][2], d2, wB.x); fma2(acc[2][3], d2, wB.y);
            fma2(acc[3][0], d3, wA.x); fma2(acc[3][1], d3, wA.y);
            fma2(acc[3][2], d3, wB.x); fma2(acc[3][3], d3, wB.y);
        }
        __syncthreads();
    }
#pragma unroll
    for (int r = 0; r < 4; r++) {
        int row = row0 + rt * 4 + r;
#pragma unroll
        for (int cp = 0; cp < 4; cp++) {
            int c0 = ct * 8 + cp * 2;
            if (c0 < PROJ) {
                float2 val = unpack2(acc[r][cp]);
                Out[(size_t)row * PROJ + c0] = val.x;
                if (c0 + 1 < PROJ) Out[(size_t)row * PROJ + c0 + 1] = val.y;
            }
        }
    }
}

// ================= kernel 2: 5x5 attention per batch + inner residual =====
__global__ __launch_bounds__(256) void attn_kernel() {
    const int b = blockIdx.x, tid = threadIdx.x;
    __shared__ float logit_s[NH * NH];
    __shared__ float attn_s[NH * NH];
    if (tid < NH * NH) logit_s[tid] = 0.f;
    __syncthreads();

    const size_t row = (size_t)(b * C_ + tid) * PROJ;

    float q50[PROJ], k50[PROJ];
#pragma unroll
    for (int t = 0; t < PROJ; t++) { q50[t] = g_Pq[row + t]; k50[t] = g_Pk[row + t]; }

#pragma unroll
    for (int i = 0; i < NH; i++)
#pragma unroll
        for (int j = 0; j < NH; j++) {
            float s = 0.f;
#pragma unroll
            for (int l = 0; l < LD; l++) s += q50[i * LD + l] * k50[j * LD + l];
            s += __shfl_xor_sync(~0u, s, 16);
            s += __shfl_xor_sync(~0u, s, 8);
            s += __shfl_xor_sync(~0u, s, 4);
            s += __shfl_xor_sync(~0u, s, 2);
            s += __shfl_xor_sync(~0u, s, 1);
            if ((tid & 31) == 0) atomicAdd(&logit_s[i * NH + j], s);
        }
    __syncthreads();

    if (tid == 0) {
        const float inv = rsqrtf((float)(C_ * LD));
        for (int i = 0; i < NH; i++) {
            float m = -1e30f;
            for (int j = 0; j < NH; j++) m = fmaxf(m, logit_s[i * NH + j] * inv);
            float e[NH], se = 0.f;
            for (int j = 0; j < NH; j++) { e[j] = expf(logit_s[i * NH + j] * inv - m); se += e[j]; }
            float rinv = 1.0f / se;
            for (int j = 0; j < NH; j++) attn_s[i * NH + j] = e[j] * rinv;
        }
    }
    __syncthreads();

    float v50[PROJ];
#pragma unroll
    for (int t = 0; t < PROJ; t++) v50[t] = g_Pv[row + t];
#pragma unroll
    for (int i = 0; i < NH; i++) {
        float a0 = attn_s[i * NH + 0], a1 = attn_s[i * NH + 1], a2 = attn_s[i * NH + 2],
              a3 = attn_s[i * NH + 3], a4 = attn_s[i * NH + 4];
#pragma unroll
        for (int l = 0; l < LD; l++) {
            g_Va2[row + i * LD + l] = v50[i * LD + l]
                + a0 * v50[l] + a1 * v50[LD + l] + a2 * v50[2 * LD + l]
                + a3 * v50[3 * LD + l] + a4 * v50[4 * LD + l];
        }
    }
}

// ================= kernel 3: out = vf + Va2 @ w_fc  (8192x50x4096) ========
#define RT2 64
#define PT2 128
__global__ __launch_bounds__(256) void fc_kernel(
    const float* __restrict__ v, const float* __restrict__ wfc,
    float* __restrict__ out)
{
    __shared__ __align__(16) float Wt[PROJ][PT2];
    __shared__ float Va2s[RT2][PROJ];
    const int p0   = blockIdx.x * PT2;
    const int row0 = blockIdx.y * RT2;
    const int tid  = threadIdx.x;

    for (int i = tid; i < PROJ * (PT2 / 4); i += 256) {
        int t = i >> 5, pj = i & 31;
        *(float4*)&Wt[t][pj * 4] = *(const float4*)(wfc + (size_t)t * HW + p0 + pj * 4);
    }
    for (int i = tid; i < RT2 * PROJ; i += 256) {
        int r = i / PROJ, t = i - r * PROJ;
        Va2s[r][t] = g_Va2[(size_t)(row0 + r) * PROJ + t];
    }
    __syncthreads();

    const int py = tid & 31;
    const int ry = tid >> 5;

    unsigned long long acc[8][2];
#pragma unroll
    for (int r = 0; r < 8; r++) { acc[r][0] = 0ull; acc[r][1] = 0ull; }

#pragma unroll
    for (int t = 0; t < PROJ; t++) {
        const ulonglong2 w2 = *(const ulonglong2*)&Wt[t][py * 4];
#pragma unroll
        for (int r = 0; r < 8; r++) {
            unsigned long long vd = pack_dup(Va2s[ry * 8 + r][t]);
            fma2(acc[r][0], vd, w2.x);
            fma2(acc[r][1], vd, w2.y);
        }
    }
#pragma unroll
    for (int r = 0; r < 8; r++) {
        int row = row0 + ry * 8 + r;
        float4 vv = *(const float4*)(v + (size_t)row * HW + p0 + py * 4);
        float2 x0 = unpack2(acc[r][0]);
        float2 x1 = unpack2(acc[r][1]);
        float4 o;
        o.x = vv.x + x0.x; o.y = vv.y + x0.y;
        o.z = vv.z + x1.x; o.w = vv.w + x1.y;
        *(float4*)(out + (size_t)row * HW + p0 + py * 4) = o;
    }
}

// ================= kernel 4: per-channel BN stats -> scale/shift ==========
__global__ __launch_bounds__(256) void stats_kernel(
    const float* __restrict__ out, const float* __restrict__ gamma,
    const float* __restrict__ beta)
{
    const int ch = blockIdx.x, tid = threadIdx.x;
    float s = 0.f, s2 = 0.f;
    for (int b = 0; b < B_; b++) {
        const float* base = out + ((size_t)(b * C_ + ch)) * HW;
#pragma unroll
        for (int i = 0; i < 4; i++) {
            float4 x = *(const float4*)(base + (tid + i * 256) * 4);
            s  += x.x + x.y + x.z + x.w;
            s2 += x.x * x.x + x.y * x.y + x.z * x.z + x.w * x.w;
        }
    }
    __shared__ float sh1[256], sh2[256];
    sh1[tid] = s; sh2[tid] = s2;
    __syncthreads();
    for (int off = 128; off > 0; off >>= 1) {
        if (tid < off) { sh1[tid] += sh1[tid + off]; sh2[tid] += sh2[tid + off]; }
        __syncthreads();
    }
    if (tid == 0) {
        const float n = (float)(B_ * HW);
        float mean = sh1[0] / n;
        float var  = sh2[0] / n - mean * mean;
        float sc = gamma[ch] * rsqrtf(var + 1e-5f);
        g_scale[ch] = sc;
        g_shift[ch] = beta[ch] - mean * sc;
    }
}

// ================= kernel 5: apply BN =====================================
__global__ __launch_bounds__(256) void bn_apply_kernel(float* __restrict__ out) {
    size_t idx4 = (size_t)blockIdx.x * 256 + threadIdx.x;
    size_t i = idx4 * 4;
    int ch = (int)((i >> 12) & (C_ - 1));
    float sc = g_scale[ch], sh = g_shift[ch];
    float4 x = *(float4*)(out + i);
    x.x = x.x * sc + sh; x.y = x.y * sc + sh;
    x.z = x.z * sc + sh; x.w = x.w * sc + sh;
    *(float4*)(out + i) = x;
}

extern "C" void kernel_launch(void* const* d_in, const int* in_sizes, int n_in,
                              void* d_out, int out_size) {
    const float* q     = (const float*)d_in[0];
    const float* k     = (const float*)d_in[1];
    const float* v     = (const float*)d_in[2];
    const float* w_q   = (const float*)d_in[3];
    const float* w_k   = (const float*)d_in[4];
    const float* w_v   = (const float*)d_in[5];
    const float* w_fc  = (const float*)d_in[6];
    const float* gamma = (const float*)d_in[7];
    const float* beta  = (const float*)d_in[8];
    float* out = (float*)d_out;

    proj_kernel<<<dim3(NROWS / TM, 3), 128>>>(q, k, v, w_q, w_k, w_v);
    attn_kernel<<<B_, 256>>>();
    fc_kernel<<<dim3(HW / PT2, NROWS / RT2), 256>>>(v, w_fc, out);
    stats_kernel<<<C_, 256>>>(out, gamma, beta);
    bn_apply_kernel<<<(NROWS * HW) / (256 * 4), 256>>>(out);
}

// round 5
// speedup vs baseline: 1.5660x; 1.5660x over previous
#include <cuda_runtime.h>
#include <cuda_bf16.h>
#include <cstdint>

#define B_    32
#define C_    256
#define HW    4096
#define NROWS (B_ * C_)
#define NH    5
#define LD    10
#define PROJ  50

// ---------------- scratch (static device memory) --------------------------
__device__ float g_Pq[NROWS * PROJ];
__device__ float g_Pk[NROWS * PROJ];
__device__ float g_Pv[NROWS * PROJ];
__device__ float g_Va2[NROWS * PROJ];
__device__ float g_scale[C_];
__device__ float g_shift[C_];
// W^T split into bf16 hi/lo: [spec][n (64 padded)][k (4096)]
__device__ __nv_bfloat16 g_WT_hi[3][64 * HW];
__device__ __nv_bfloat16 g_WT_lo[3][64 * HW];

// ---------------- packed f32x2 helpers (for fc kernel) --------------------
__device__ __forceinline__ unsigned long long pack_dup(float x) {
    unsigned long long r; unsigned u = __float_as_uint(x);
    asm("mov.b64 %0, {%1, %1};" : "=l"(r) : "r"(u));
    return r;
}
__device__ __forceinline__ void fma2(unsigned long long &acc,
                                     unsigned long long a, unsigned long long b) {
    asm("fma.rn.f32x2 %0, %1, %2, %0;" : "+l"(acc) : "l"(a), "l"(b));
}
__device__ __forceinline__ float2 unpack2(unsigned long long p) {
    unsigned lo, hi;
    asm("mov.b64 {%0, %1}, %2;" : "=r"(lo), "=r"(hi) : "l"(p));
    return make_float2(__uint_as_float(lo), __uint_as_float(hi));
}

// ---------------- HMMA 16x8x16 bf16 (baseline PTX, works on sm_103) -------
__device__ __forceinline__ void mma16816(float* c, const uint32_t* a, const uint32_t* b) {
    asm volatile("mma.sync.aligned.m16n8k16.row.col.f32.bf16.bf16.f32 "
        "{%0,%1,%2,%3}, {%4,%5,%6,%7}, {%8,%9}, {%0,%1,%2,%3};"
        : "+f"(c[0]), "+f"(c[1]), "+f"(c[2]), "+f"(c[3])
        : "r"(a[0]), "r"(a[1]), "r"(a[2]), "r"(a[3]), "r"(b[0]), "r"(b[1]));
}

// ================= kernel 0: W^T bf16 hi/lo prep ==========================
__global__ __launch_bounds__(256) void prep_w_kernel(
    const float* __restrict__ wq, const float* __restrict__ wk,
    const float* __restrict__ wv)
{
    const int spec = blockIdx.y;
    const float* W = (spec == 0) ? wq : (spec == 1) ? wk : wv;
    const int n = blockIdx.x;  // 0..63
    for (int kk = threadIdx.x; kk < HW; kk += 256) {
        float x = (n < PROJ) ? W[(size_t)kk * PROJ + n] : 0.f;
        __nv_bfloat16 h = __float2bfloat16(x);
        float lo = x - __bfloat162float(h);
        g_WT_hi[spec][n * HW + kk] = h;
        g_WT_lo[spec][n * HW + kk] = __float2bfloat16(lo);
    }
}

// ================= kernel 1: proj via mma.sync bf16-split =================
// Out[row, n] = sum_k A[row,k] * WT[n,k].   M-tile 128, N=64, K-chunk 32.
// 128 threads = 4 warps; each warp owns 32 rows (2 m16 tiles) x 8 n8 tiles.
#define MT 128
#define KC 32
__global__ __launch_bounds__(128) void proj_mma_kernel(
    const float* __restrict__ q, const float* __restrict__ k,
    const float* __restrict__ v)
{
    __shared__ __nv_bfloat16 Ah[MT][KC], Al[MT][KC];
    __shared__ __nv_bfloat16 Bh[64][KC], Bl[64][KC];

    const int spec = blockIdx.y;
    const float* A = (spec == 0) ? q : (spec == 1) ? k : v;
    const __nv_bfloat16* WTh = g_WT_hi[spec];
    const __nv_bfloat16* WTl = g_WT_lo[spec];
    float* Out = (spec == 0) ? g_Pq : (spec == 1) ? g_Pk : g_Pv;

    const int row0 = blockIdx.x * MT;
    const int tid  = threadIdx.x;
    const int wid  = tid >> 5, lane = tid & 31;
    const int gr = lane >> 2, tq = lane & 3;

    float acc[2][8][4];
#pragma unroll
    for (int mt = 0; mt < 2; mt++)
#pragma unroll
        for (int nt = 0; nt < 8; nt++)
#pragma unroll
            for (int i = 0; i < 4; i++) acc[mt][nt][i] = 0.f;

    for (int kc = 0; kc < HW / KC; kc++) {
        const int k0 = kc * KC;
        // ---- stage A: 128 rows x 32 fp32 -> bf16 hi(trunc)/lo ----
#pragma unroll
        for (int j = 0; j < 8; j++) {
            int i = tid + j * 128;           // 1024 float4
            int r = i >> 3, c4 = (i & 7) * 4;
            float4 x = *(const float4*)(A + (size_t)(row0 + r) * HW + k0 + c4);
            uint32_t ux = __float_as_uint(x.x), uy = __float_as_uint(x.y);
            uint32_t uz = __float_as_uint(x.z), uw = __float_as_uint(x.w);
            uint32_t hi01 = __byte_perm(ux, uy, 0x7632);
            uint32_t hi23 = __byte_perm(uz, uw, 0x7632);
            float l0 = x.x - __uint_as_float(ux & 0xFFFF0000u);
            float l1 = x.y - __uint_as_float(uy & 0xFFFF0000u);
            float l2 = x.z - __uint_as_float(uz & 0xFFFF0000u);
            float l3 = x.w - __uint_as_float(uw & 0xFFFF0000u);
            __nv_bfloat162 lo01 = __float22bfloat162_rn(make_float2(l0, l1));
            __nv_bfloat162 lo23 = __float22bfloat162_rn(make_float2(l2, l3));
            *(uint2*)&Ah[r][c4] = make_uint2(hi01, hi23);
            *(uint2*)&Al[r][c4] = make_uint2(*(uint32_t*)&lo01, *(uint32_t*)&lo23);
        }
        // ---- stage B: 64 n x 32 k, hi+lo copies ----
#pragma unroll
        for (int j = 0; j < 2; j++) {
            int i = tid + j * 128;           // 256 uint4 per split
            int n = i >> 2, k8 = (i & 3) * 8;
            *(uint4*)&Bh[n][k8] = *(const uint4*)(WTh + (size_t)n * HW + k0 + k8);
            *(uint4*)&Bl[n][k8] = *(const uint4*)(WTl + (size_t)n * HW + k0 + k8);
        }
        __syncthreads();

        // ---- mma: two k16 steps ----
#pragma unroll
        for (int ks = 0; ks < KC; ks += 16) {
            uint32_t ah[2][4], al[2][4], bh[8][2], bl[8][2];
#pragma unroll
            for (int mt = 0; mt < 2; mt++) {
                int r = wid * 32 + mt * 16 + gr;
                int kb = ks + tq * 2;
                ah[mt][0] = *(const uint32_t*)&Ah[r][kb];
                ah[mt][1] = *(const uint32_t*)&Ah[r + 8][kb];
                ah[mt][2] = *(const uint32_t*)&Ah[r][kb + 8];
                ah[mt][3] = *(const uint32_t*)&Ah[r + 8][kb + 8];
                al[mt][0] = *(const uint32_t*)&Al[r][kb];
                al[mt][1] = *(const uint32_t*)&Al[r + 8][kb];
                al[mt][2] = *(const uint32_t*)&Al[r][kb + 8];
                al[mt][3] = *(const uint32_t*)&Al[r + 8][kb + 8];
            }
#pragma unroll
            for (int nt = 0; nt < 8; nt++) {
                int n = nt * 8 + gr;
                int kb = ks + tq * 2;
                bh[nt][0] = *(const uint32_t*)&Bh[n][kb];
                bh[nt][1] = *(const uint32_t*)&Bh[n][kb + 8];
                bl[nt][0] = *(const uint32_t*)&Bl[n][kb];
                bl[nt][1] = *(const uint32_t*)&Bl[n][kb + 8];
            }
#pragma unroll
            for (int mt = 0; mt < 2; mt++)
#pragma unroll
                for (int nt = 0; nt < 8; nt++) {
                    mma16816(acc[mt][nt], ah[mt], bh[nt]);
                    mma16816(acc[mt][nt], ah[mt], bl[nt]);
                    mma16816(acc[mt][nt], al[mt], bh[nt]);
                }
        }
        __syncthreads();
    }

    // ---- epilogue ----
#pragma unroll
    for (int mt = 0; mt < 2; mt++) {
        int rbase = row0 + wid * 32 + mt * 16 + gr;
#pragma unroll
        for (int nt = 0; nt < 8; nt++) {
            int col = nt * 8 + tq * 2;
            if (col < PROJ) {
                Out[(size_t)rbase * PROJ + col]           = acc[mt][nt][0];
                Out[(size_t)rbase * PROJ + col + 1]       = acc[mt][nt][1];
                Out[(size_t)(rbase + 8) * PROJ + col]     = acc[mt][nt][2];
                Out[(size_t)(rbase + 8) * PROJ + col + 1] = acc[mt][nt][3];
            }
        }
    }
}

// ================= kernel 2: 5x5 attention per batch + inner residual =====
__global__ __launch_bounds__(256) void attn_kernel() {
    const int b = blockIdx.x, tid = threadIdx.x;
    __shared__ float logit_s[NH * NH];
    __shared__ float attn_s[NH * NH];
    if (tid < NH * NH) logit_s[tid] = 0.f;
    __syncthreads();

    const size_t row = (size_t)(b * C_ + tid) * PROJ;

    float q50[PROJ], k50[PROJ];
#pragma unroll
    for (int t = 0; t < PROJ; t++) { q50[t] = g_Pq[row + t]; k50[t] = g_Pk[row + t]; }

#pragma unroll
    for (int i = 0; i < NH; i++)
#pragma unroll
        for (int j = 0; j < NH; j++) {
            float s = 0.f;
#pragma unroll
            for (int l = 0; l < LD; l++) s += q50[i * LD + l] * k50[j * LD + l];
            s += __shfl_xor_sync(~0u, s, 16);
            s += __shfl_xor_sync(~0u, s, 8);
            s += __shfl_xor_sync(~0u, s, 4);
            s += __shfl_xor_sync(~0u, s, 2);
            s += __shfl_xor_sync(~0u, s, 1);
            if ((tid & 31) == 0) atomicAdd(&logit_s[i * NH + j], s);
        }
    __syncthreads();

    if (tid == 0) {
        const float inv = rsqrtf((float)(C_ * LD));
        for (int i = 0; i < NH; i++) {
            float m = -1e30f;
            for (int j = 0; j < NH; j++) m = fmaxf(m, logit_s[i * NH + j] * inv);
            float e[NH], se = 0.f;
            for (int j = 0; j < NH; j++) { e[j] = expf(logit_s[i * NH + j] * inv - m); se += e[j]; }
            float rinv = 1.0f / se;
            for (int j = 0; j < NH; j++) attn_s[i * NH + j] = e[j] * rinv;
        }
    }
    __syncthreads();

    float v50[PROJ];
#pragma unroll
    for (int t = 0; t < PROJ; t++) v50[t] = g_Pv[row + t];
#pragma unroll
    for (int i = 0; i < NH; i++) {
        float a0 = attn_s[i * NH + 0], a1 = attn_s[i * NH + 1], a2 = attn_s[i * NH + 2],
              a3 = attn_s[i * NH + 3], a4 = attn_s[i * NH + 4];
#pragma unroll
        for (int l = 0; l < LD; l++) {
            g_Va2[row + i * LD + l] = v50[i * LD + l]
                + a0 * v50[l] + a1 * v50[LD + l] + a2 * v50[2 * LD + l]
                + a3 * v50[3 * LD + l] + a4 * v50[4 * LD + l];
        }
    }
}

// ================= kernel 3: out = vf + Va2 @ w_fc  (8192x50x4096) ========
#define RT2 64
#define PT2 128
__global__ __launch_bounds__(256) void fc_kernel(
    const float* __restrict__ v, const float* __restrict__ wfc,
    float* __restrict__ out)
{
    __shared__ __align__(16) float Wt[PROJ][PT2];
    __shared__ float Va2s[RT2][PROJ];
    const int p0   = blockIdx.x * PT2;
    const int row0 = blockIdx.y * RT2;
    const int tid  = threadIdx.x;

    for (int i = tid; i < PROJ * (PT2 / 4); i += 256) {
        int t = i >> 5, pj = i & 31;
        *(float4*)&Wt[t][pj * 4] = *(const float4*)(wfc + (size_t)t * HW + p0 + pj * 4);
    }
    for (int i = tid; i < RT2 * PROJ; i += 256) {
        int r = i / PROJ, t = i - r * PROJ;
        Va2s[r][t] = g_Va2[(size_t)(row0 + r) * PROJ + t];
    }
    __syncthreads();

    const int py = tid & 31;
    const int ry = tid >> 5;

    unsigned long long acc[8][2];
#pragma unroll
    for (int r = 0; r < 8; r++) { acc[r][0] = 0ull; acc[r][1] = 0ull; }

#pragma unroll
    for (int t = 0; t < PROJ; t++) {
        const ulonglong2 w2 = *(const ulonglong2*)&Wt[t][py * 4];
#pragma unroll
        for (int r = 0; r < 8; r++) {
            unsigned long long vd = pack_dup(Va2s[ry * 8 + r][t]);
            fma2(acc[r][0], vd, w2.x);
            fma2(acc[r][1], vd, w2.y);
        }
    }
#pragma unroll
    for (int r = 0; r < 8; r++) {
        int row = row0 + ry * 8 + r;
        float4 vv = *(const float4*)(v + (size_t)row * HW + p0 + py * 4);
        float2 x0 = unpack2(acc[r][0]);
        float2 x1 = unpack2(acc[r][1]);
        float4 o;
        o.x = vv.x + x0.x; o.y = vv.y + x0.y;
        o.z = vv.z + x1.x; o.w = vv.w + x1.y;
        *(float4*)(out + (size_t)row * HW + p0 + py * 4) = o;
    }
}

// ================= kernel 4: per-channel BN stats -> scale/shift ==========
__global__ __launch_bounds__(256) void stats_kernel(
    const float* __restrict__ out, const float* __restrict__ gamma,
    const float* __restrict__ beta)
{
    const int ch = blockIdx.x, tid = threadIdx.x;
    float s = 0.f, s2 = 0.f;
    for (int b = 0; b < B_; b++) {
        const float* base = out + ((size_t)(b * C_ + ch)) * HW;
#pragma unroll
        for (int i = 0; i < 4; i++) {
            float4 x = *(const float4*)(base + (tid + i * 256) * 4);
            s  += x.x + x.y + x.z + x.w;
            s2 += x.x * x.x + x.y * x.y + x.z * x.z + x.w * x.w;
        }
    }
    __shared__ float sh1[256], sh2[256];
    sh1[tid] = s; sh2[tid] = s2;
    __syncthreads();
    for (int off = 128; off > 0; off >>= 1) {
        if (tid < off) { sh1[tid] += sh1[tid + off]; sh2[tid] += sh2[tid + off]; }
        __syncthreads();
    }
    if (tid == 0) {
        const float n = (float)(B_ * HW);
        float mean = sh1[0] / n;
        float var  = sh2[0] / n - mean * mean;
        float sc = gamma[ch] * rsqrtf(var + 1e-5f);
        g_scale[ch] = sc;
        g_shift[ch] = beta[ch] - mean * sc;
    }
}

// ================= kernel 5: apply BN =====================================
__global__ __launch_bounds__(256) void bn_apply_kernel(float* __restrict__ out) {
    size_t idx4 = (size_t)blockIdx.x * 256 + threadIdx.x;
    size_t i = idx4 * 4;
    int ch = (int)((i >> 12) & (C_ - 1));
    float sc = g_scale[ch], sh = g_shift[ch];
    float4 x = *(float4*)(out + i);
    x.x = x.x * sc + sh; x.y = x.y * sc + sh;
    x.z = x.z * sc + sh; x.w = x.w * sc + sh;
    *(float4*)(out + i) = x;
}

extern "C" void kernel_launch(void* const* d_in, const int* in_sizes, int n_in,
                              void* d_out, int out_size) {
    const float* q     = (const float*)d_in[0];
    const float* k     = (const float*)d_in[1];
    const float* v     = (const float*)d_in[2];
    const float* w_q   = (const float*)d_in[3];
    const float* w_k   = (const float*)d_in[4];
    const float* w_v   = (const float*)d_in[5];
    const float* w_fc  = (const float*)d_in[6];
    const float* gamma = (const float*)d_in[7];
    const float* beta  = (const float*)d_in[8];
    float* out = (float*)d_out;

    prep_w_kernel<<<dim3(64, 3), 256>>>(w_q, w_k, w_v);
    proj_mma_kernel<<<dim3(NROWS / MT, 3), 128>>>(q, k, v);
    attn_kernel<<<B_, 256>>>();
    fc_kernel<<<dim3(HW / PT2, NROWS / RT2), 256>>>(v, w_fc, out);
    stats_kernel<<<C_, 256>>>(out, gamma, beta);
    bn_apply_kernel<<<(NROWS * HW) / (256 * 4), 256>>>(out);
}

// round 7
// speedup vs baseline: 2.3443x; 1.4970x over previous
#include <cuda_runtime.h>
#include <cuda_bf16.h>
#include <cstdint>

#define B_    32
#define C_    256
#define HW    4096
#define NROWS (B_ * C_)
#define NH    5
#define LD    10
#define PROJ  50

// ---------------- scratch (static device memory) --------------------------
__device__ float g_Pq[NROWS * PROJ];
__device__ float g_Pk[NROWS * PROJ];
__device__ float g_Pv[NROWS * PROJ];
__device__ float g_scale[C_];
__device__ float g_shift[C_];
__device__ float g_bnsum[C_];
__device__ float g_bnsum2[C_];
// W^T split into bf16 hi/lo: [spec][n (64 padded)][k (4096)]
__device__ __nv_bfloat16 g_WT_hi[3][64 * HW];
__device__ __nv_bfloat16 g_WT_lo[3][64 * HW];
// Va2 (attn output) bf16 hi/lo, [row][64] (cols 50..63 stay zero)
__device__ __nv_bfloat16 g_Va2h[NROWS * 64];
__device__ __nv_bfloat16 g_Va2l[NROWS * 64];
// w_fc transposed+split: [n=4096][k=64] (k 50..63 zero)
__device__ __nv_bfloat16 g_WfcTh[HW * 64];
__device__ __nv_bfloat16 g_WfcTl[HW * 64];

// ---------------- helpers --------------------------------------------------
__device__ __forceinline__ uint32_t smem_u32(const void* p) {
    uint32_t a;
    asm("{ .reg .u64 t; cvta.to.shared.u64 t, %1; cvt.u32.u64 %0, t; }" : "=r"(a) : "l"(p));
    return a;
}
__device__ __forceinline__ void mma16816(float* c, const uint32_t* a, const uint32_t* b) {
    asm volatile("mma.sync.aligned.m16n8k16.row.col.f32.bf16.bf16.f32 "
        "{%0,%1,%2,%3}, {%4,%5,%6,%7}, {%8,%9}, {%0,%1,%2,%3};"
        : "+f"(c[0]), "+f"(c[1]), "+f"(c[2]), "+f"(c[3])
        : "r"(a[0]), "r"(a[1]), "r"(a[2]), "r"(a[3]), "r"(b[0]), "r"(b[1]));
}
__device__ __forceinline__ void ldm_x4(uint32_t* r, uint32_t addr) {
    asm volatile("ldmatrix.sync.aligned.m8n8.x4.shared.b16 {%0,%1,%2,%3}, [%4];"
        : "=r"(r[0]), "=r"(r[1]), "=r"(r[2]), "=r"(r[3]) : "r"(addr));
}

// ================= kernel: zero BN accumulators ===========================
__global__ void init_kernel() {
    int t = threadIdx.x;
    if (t < C_) { g_bnsum[t] = 0.f; g_bnsum2[t] = 0.f; }
}

// ================= kernel 0a: W^T bf16 hi/lo prep =========================
__global__ __launch_bounds__(256) void prep_w_kernel(
    const float* __restrict__ wq, const float* __restrict__ wk,
    const float* __restrict__ wv)
{
    const int spec = blockIdx.y;
    const float* W = (spec == 0) ? wq : (spec == 1) ? wk : wv;
    const int n = blockIdx.x;  // 0..63
    for (int kk = threadIdx.x; kk < HW; kk += 256) {
        float x = (n < PROJ) ? W[(size_t)kk * PROJ + n] : 0.f;
        __nv_bfloat16 h = __float2bfloat16(x);
        float lo = x - __bfloat162float(h);
        g_WT_hi[spec][n * HW + kk] = h;
        g_WT_lo[spec][n * HW + kk] = __float2bfloat16(lo);
    }
}

// ================= kernel 0b: w_fc transpose+split ========================
__global__ __launch_bounds__(256) void prep_wfc_kernel(const float* __restrict__ wfc) {
    const int n = blockIdx.x * 256 + threadIdx.x;   // 0..4095
#pragma unroll 1
    for (int kk = 0; kk < 64; kk++) {
        float x = (kk < PROJ) ? wfc[(size_t)kk * HW + n] : 0.f;
        __nv_bfloat16 h = __float2bfloat16(x);
        float lo = x - __bfloat162float(h);
        g_WfcTh[(size_t)n * 64 + kk] = h;
        g_WfcTl[(size_t)n * 64 + kk] = __float2bfloat16(lo);
    }
}

// ================= kernel 1: proj via mma.sync bf16-split =================
// Out[row, n] = sum_k A[row,k] * WT[n,k].  M-tile 64, N=64, K-chunk 64.
// 128 threads = 4 warps; warp w owns rows w*16..w*16+15; 8 n8-tiles each.
#define PMT 64
#define PKC 64
#define PAD 72
__global__ __launch_bounds__(128) void proj_mma_kernel(
    const float* __restrict__ q, const float* __restrict__ k,
    const float* __restrict__ v)
{
    __shared__ __nv_bfloat16 Ah[PMT][PAD], Al[PMT][PAD];
    __shared__ __nv_bfloat16 Bh[64][PAD],  Bl[64][PAD];

    const int spec = blockIdx.y;
    const float* A = (spec == 0) ? q : (spec == 1) ? k : v;
    const __nv_bfloat16* WTh = g_WT_hi[spec];
    const __nv_bfloat16* WTl = g_WT_lo[spec];
    float* Out = (spec == 0) ? g_Pq : (spec == 1) ? g_Pk : g_Pv;

    const int row0 = blockIdx.x * PMT;
    const int tid  = threadIdx.x;
    const int wid  = tid >> 5, lane = tid & 31;
    const int gr = lane >> 2, tq = lane & 3;

    // ldmatrix source addresses (constant across k-chunks except +ks*2B)
    const int a_row = wid * 16 + (lane & 15);
    const int a_k   = (lane >> 4) << 3;
    const uint32_t sAh = smem_u32(&Ah[a_row][a_k]);
    const uint32_t sAl = smem_u32(&Al[a_row][a_k]);
    const int b_n = ((lane >> 4) << 3) + (lane & 7);
    const int b_k = ((lane >> 3) & 1) << 3;
    const uint32_t sBh = smem_u32(&Bh[b_n][b_k]);
    const uint32_t sBl = smem_u32(&Bl[b_n][b_k]);

    float acc[8][4];
#pragma unroll
    for (int nt = 0; nt < 8; nt++)
#pragma unroll
        for (int i = 0; i < 4; i++) acc[nt][i] = 0.f;

    for (int kc = 0; kc < HW / PKC; kc++) {
        const int k0 = kc * PKC;
        // ---- A: 64 rows x 64 fp32 -> bf16 hi(trunc)/lo into padded smem ----
#pragma unroll
        for (int j = 0; j < 8; j++) {
            int i = tid + j * 128;              // 1024 float4
            int r = i >> 4, c4 = (i & 15) * 4;
            float4 x = *(const float4*)(A + (size_t)(row0 + r) * HW + k0 + c4);
            uint32_t ux = __float_as_uint(x.x), uy = __float_as_uint(x.y);
            uint32_t uz = __float_as_uint(x.z), uw = __float_as_uint(x.w);
            uint32_t hi01 = __byte_perm(ux, uy, 0x7632);
            uint32_t hi23 = __byte_perm(uz, uw, 0x7632);
            float l0 = x.x - __uint_as_float(ux & 0xFFFF0000u);
            float l1 = x.y - __uint_as_float(uy & 0xFFFF0000u);
            float l2 = x.z - __uint_as_float(uz & 0xFFFF0000u);
            float l3 = x.w - __uint_as_float(uw & 0xFFFF0000u);
            __nv_bfloat162 lo01 = __float22bfloat162_rn(make_float2(l0, l1));
            __nv_bfloat162 lo23 = __float22bfloat162_rn(make_float2(l2, l3));
            *(uint2*)&Ah[r][c4] = make_uint2(hi01, hi23);
            *(uint2*)&Al[r][c4] = make_uint2(*(uint32_t*)&lo01, *(uint32_t*)&lo23);
        }
        // ---- B: 64 n x 64 k, hi+lo ----
#pragma unroll
        for (int j = 0; j < 4; j++) {
            int i = tid + j * 128;              // 512 uint4 per split
            int n = i >> 3, k8 = (i & 7) * 8;
            *(uint4*)&Bh[n][k8] = *(const uint4*)(WTh + (size_t)n * HW + k0 + k8);
            *(uint4*)&Bl[n][k8] = *(const uint4*)(WTl + (size_t)n * HW + k0 + k8);
        }
        __syncthreads();

#pragma unroll
        for (int ksi = 0; ksi < 4; ksi++) {
            const uint32_t koff = ksi * 32;     // 16 bf16 = 32 bytes
            uint32_t ah[4], al[4];
            ldm_x4(ah, sAh + koff);
            ldm_x4(al, sAl + koff);
#pragma unroll
            for (int g = 0; g < 4; g++) {
                uint32_t bh4[4], bl4[4];
                const uint32_t boff = g * 16 * (PAD * 2) + koff;
                ldm_x4(bh4, sBh + boff);
                ldm_x4(bl4, sBl + boff);
                mma16816(acc[2 * g],     ah, bh4);
                mma16816(acc[2 * g],     ah, bl4);
                mma16816(acc[2 * g],     al, bh4);
                mma16816(acc[2 * g + 1], ah, bh4 + 2);
                mma16816(acc[2 * g + 1], ah, bl4 + 2);
                mma16816(acc[2 * g + 1], al, bh4 + 2);
            }
        }
        __syncthreads();
    }

    // ---- epilogue ----
    const int r0 = row0 + wid * 16 + gr;
#pragma unroll
    for (int nt = 0; nt < 8; nt++) {
        int col = nt * 8 + tq * 2;
        if (col < PROJ) {
            Out[(size_t)r0 * PROJ + col]           = acc[nt][0];
            Out[(size_t)r0 * PROJ + col + 1]       = acc[nt][1];
            Out[(size_t)(r0 + 8) * PROJ + col]     = acc[nt][2];
            Out[(size_t)(r0 + 8) * PROJ + col + 1] = acc[nt][3];
        }
    }
}

// ================= kernel 2: 5x5 attention + inner residual ===============
// Writes Va2 as bf16 hi/lo into padded [row][64] buffers.
__global__ __launch_bounds__(256) void attn_kernel() {
    const int b = blockIdx.x, tid = threadIdx.x;
    __shared__ float logit_s[NH * NH];
    __shared__ float attn_s[NH * NH];
    if (tid < NH * NH) logit_s[tid] = 0.f;
    __syncthreads();

    const size_t row = (size_t)(b * C_ + tid);
    const size_t rp = row * PROJ;

    float q50[PROJ], k50[PROJ];
#pragma unroll
    for (int t = 0; t < PROJ; t++) { q50[t] = g_Pq[rp + t]; k50[t] = g_Pk[rp + t]; }

#pragma unroll
    for (int i = 0; i < NH; i++)
#pragma unroll
        for (int j = 0; j < NH; j++) {
            float s = 0.f;
#pragma unroll
            for (int l = 0; l < LD; l++) s += q50[i * LD + l] * k50[j * LD + l];
            s += __shfl_xor_sync(~0u, s, 16);
            s += __shfl_xor_sync(~0u, s, 8);
            s += __shfl_xor_sync(~0u, s, 4);
            s += __shfl_xor_sync(~0u, s, 2);
            s += __shfl_xor_sync(~0u, s, 1);
            if ((tid & 31) == 0) atomicAdd(&logit_s[i * NH + j], s);
        }
    __syncthreads();

    if (tid == 0) {
        const float inv = rsqrtf((float)(C_ * LD));
        for (int i = 0; i < NH; i++) {
            float m = -1e30f;
            for (int j = 0; j < NH; j++) m = fmaxf(m, logit_s[i * NH + j] * inv);
            float e[NH], se = 0.f;
            for (int j = 0; j < NH; j++) { e[j] = expf(logit_s[i * NH + j] * inv - m); se += e[j]; }
            float rinv = 1.0f / se;
            for (int j = 0; j < NH; j++) attn_s[i * NH + j] = e[j] * rinv;
        }
    }
    __syncthreads();

    float v50[PROJ];
#pragma unroll
    for (int t = 0; t < PROJ; t++) v50[t] = g_Pv[rp + t];
#pragma unroll
    for (int i = 0; i < NH; i++) {
        float a0 = attn_s[i * NH + 0], a1 = attn_s[i * NH + 1], a2 = attn_s[i * NH + 2],
              a3 = attn_s[i * NH + 3], a4 = attn_s[i * NH + 4];
#pragma unroll
        for (int l = 0; l < LD; l++) {
            float s = v50[i * LD + l]
                + a0 * v50[l] + a1 * v50[LD + l] + a2 * v50[2 * LD + l]
                + a3 * v50[3 * LD + l] + a4 * v50[4 * LD + l];
            __nv_bfloat16 h = __float2bfloat16(s);
            float lo = s - __bfloat162float(h);
            g_Va2h[row * 64 + i * LD + l] = h;
            g_Va2l[row * 64 + i * LD + l] = __float2bfloat16(lo);
        }
    }
}

// ================= kernel 3: fc via mma.sync + residual + BN stats ========
// out[row, n] = v[row, n] + sum_k Va2[row,k] * WfcT[n,k];  K=64 one pass.
// Tile M=128, N=128, 256 threads (8 warps, warp = 16 rows x 128 cols).
#define FMT 128
#define FNT 128
__global__ __launch_bounds__(256) void fc_mma_kernel(
    const float* __restrict__ v, float* __restrict__ out)
{
    extern __shared__ char fsm[];
    __nv_bfloat16* Ah = (__nv_bfloat16*)fsm;            // [128][72]
    __nv_bfloat16* Al = Ah + FMT * PAD;
    __nv_bfloat16* Bh = Al + FMT * PAD;                 // [128][72]
    __nv_bfloat16* Bl = Bh + FNT * PAD;

    const int n0   = blockIdx.x * FNT;
    const int row0 = blockIdx.y * FMT;
    const int tid  = threadIdx.x;
    const int wid  = tid >> 5, lane = tid & 31;
    const int gr = lane >> 2, tq = lane & 3;

    // load A (Va2 hi/lo) and B (WfcT hi/lo) tiles: 8 uint4 per row
#pragma unroll
    for (int j = 0; j < 4; j++) {
        int i = tid + j * 256;                  // 1024 uint4
        int r = i >> 3, k8 = (i & 7) * 8;
        *(uint4*)&Ah[r * PAD + k8] = *(const uint4*)&g_Va2h[(size_t)(row0 + r) * 64 + k8];
        *(uint4*)&Al[r * PAD + k8] = *(const uint4*)&g_Va2l[(size_t)(row0 + r) * 64 + k8];
        *(uint4*)&Bh[r * PAD + k8] = *(const uint4*)&g_WfcTh[(size_t)(n0 + r) * 64 + k8];
        *(uint4*)&Bl[r * PAD + k8] = *(const uint4*)&g_WfcTl[(size_t)(n0 + r) * 64 + k8];
    }
    __syncthreads();

    const int a_row = wid * 16 + (lane & 15);
    const int a_k   = (lane >> 4) << 3;
    const uint32_t sAh = smem_u32(&Ah[a_row * PAD + a_k]);
    const uint32_t sAl = smem_u32(&Al[a_row * PAD + a_k]);
    const int b_n = ((lane >> 4) << 3) + (lane & 7);
    const int b_k = ((lane >> 3) & 1) << 3;
    const uint32_t sBh = smem_u32(&Bh[b_n * PAD + b_k]);
    const uint32_t sBl = smem_u32(&Bl[b_n * PAD + b_k]);

    float acc[16][4];
#pragma unroll
    for (int nt = 0; nt < 16; nt++)
#pragma unroll
        for (int i = 0; i < 4; i++) acc[nt][i] = 0.f;

#pragma unroll
    for (int ksi = 0; ksi < 4; ksi++) {
        const uint32_t koff = ksi * 32;
        uint32_t ah[4], al[4];
        ldm_x4(ah, sAh + koff);
        ldm_x4(al, sAl + koff);
#pragma unroll
        for (int g = 0; g < 8; g++) {
            uint32_t bh4[4], bl4[4];
            const uint32_t boff = g * 16 * (PAD * 2) + koff;
            ldm_x4(bh4, sBh + boff);
            ldm_x4(bl4, sBl + boff);
            mma16816(acc[2 * g],     ah, bh4);
            mma16816(acc[2 * g],     ah, bl4);
            mma16816(acc[2 * g],     al, bh4);
            mma16816(acc[2 * g + 1], ah, bh4 + 2);
            mma16816(acc[2 * g + 1], ah, bl4 + 2);
            mma16816(acc[2 * g + 1], al, bh4 + 2);
        }
    }

    // ---- epilogue: residual + store + BN partial sums ----
    const int r0 = row0 + wid * 16 + gr;
    const int r1 = r0 + 8;
    float s0 = 0.f, s20 = 0.f, s1 = 0.f, s21 = 0.f;
#pragma unroll
    for (int nt = 0; nt < 16; nt++) {
        int col = n0 + nt * 8 + tq * 2;
        float2 v0 = *(const float2*)(v + (size_t)r0 * HW + col);
        float2 v1 = *(const float2*)(v + (size_t)r1 * HW + col);
        float o00 = v0.x + acc[nt][0], o01 = v0.y + acc[nt][1];
        float o10 = v1.x + acc[nt][2], o11 = v1.y + acc[nt][3];
        *(float2*)(out + (size_t)r0 * HW + col) = make_float2(o00, o01);
        *(float2*)(out + (size_t)r1 * HW + col) = make_float2(o10, o11);
        s0  += o00 + o01;        s1  += o10 + o11;
        s20 += o00 * o00 + o01 * o01;
        s21 += o10 * o10 + o11 * o11;
    }
    // reduce over the quad (lanes gr*4 + tq)
    s0  += __shfl_xor_sync(~0u, s0, 1);  s0  += __shfl_xor_sync(~0u, s0, 2);
    s1  += __shfl_xor_sync(~0u, s1, 1);  s1  += __shfl_xor_sync(~0u, s1, 2);
    s20 += __shfl_xor_sync(~0u, s20, 1); s20 += __shfl_xor_sync(~0u, s20, 2);
    s21 += __shfl_xor_sync(~0u, s21, 1); s21 += __shfl_xor_sync(~0u, s21, 2);
    if (tq == 0) {
        atomicAdd(&g_bnsum[r0 & (C_ - 1)], s0);
        atomicAdd(&g_bnsum2[r0 & (C_ - 1)], s20);
        atomicAdd(&g_bnsum[r1 & (C_ - 1)], s1);
        atomicAdd(&g_bnsum2[r1 & (C_ - 1)], s21);
    }
}

// ================= kernel 4: finalize BN scale/shift ======================
__global__ void finalize_kernel(const float* __restrict__ gamma,
                                const float* __restrict__ beta) {
    int ch = threadIdx.x;
    if (ch < C_) {
        const float n = (float)(B_ * HW);
        float mean = g_bnsum[ch] / n;
        float var  = g_bnsum2[ch] / n - mean * mean;
        float sc = gamma[ch] * rsqrtf(var + 1e-5f);
        g_scale[ch] = sc;
        g_shift[ch] = beta[ch] - mean * sc;
    }
}

// ================= kernel 5: apply BN =====================================
__global__ __launch_bounds__(256) void bn_apply_kernel(float* __restrict__ out) {
    size_t idx4 = (size_t)blockIdx.x * 256 + threadIdx.x;
    size_t i = idx4 * 4;
    int ch = (int)((i >> 12) & (C_ - 1));
    float sc = g_scale[ch], sh = g_shift[ch];
    float4 x = *(float4*)(out + i);
    x.x = x.x * sc + sh; x.y = x.y * sc + sh;
    x.z = x.z * sc + sh; x.w = x.w * sc + sh;
    *(float4*)(out + i) = x;
}

extern "C" void kernel_launch(void* const* d_in, const int* in_sizes, int n_in,
                              void* d_out, int out_size) {
    const float* q     = (const float*)d_in[0];
    const float* k     = (const float*)d_in[1];
    const float* v     = (const float*)d_in[2];
    const float* w_q   = (const float*)d_in[3];
    const float* w_k   = (const float*)d_in[4];
    const float* w_v   = (const float*)d_in[5];
    const float* w_fc  = (const float*)d_in[6];
    const float* gamma = (const float*)d_in[7];
    const float* beta  = (const float*)d_in[8];
    float* out = (float*)d_out;

    const int FC_SMEM = 4 * FMT * PAD * 2;   // 73728 bytes
    cudaFuncSetAttribute(fc_mma_kernel,
                         cudaFuncAttributeMaxDynamicSharedMemorySize, FC_SMEM);

    init_kernel<<<1, 256>>>();
    prep_w_kernel<<<dim3(64, 3), 256>>>(w_q, w_k, w_v);
    prep_wfc_kernel<<<HW / 256, 256>>>(w_fc);
    proj_mma_kernel<<<dim3(NROWS / PMT, 3), 128>>>(q, k, v);
    attn_kernel<<<B_, 256>>>();
    fc_mma_kernel<<<dim3(HW / FNT, NROWS / FMT), 256, FC_SMEM>>>(v, out);
    finalize_kernel<<<1, 256>>>(gamma, beta);
    bn_apply_kernel<<<(NROWS * HW) / (256 * 4), 256>>>(out);
}

// round 8
// speedup vs baseline: 3.0420x; 1.2976x over previous
#include <cuda_runtime.h>
#include <cuda_bf16.h>
#include <cstdint>

#define B_    32
#define C_    256
#define HW    4096
#define NROWS (B_ * C_)
#define NH    5
#define LD    10
#define PROJ  50

// ---------------- scratch (static device memory) --------------------------
__device__ float g_Pq[NROWS * PROJ];
__device__ float g_Pk[NROWS * PROJ];
__device__ float g_Pv[NROWS * PROJ];
__device__ float g_scale[C_];
__device__ float g_shift[C_];
__device__ float g_bnsum[C_];
__device__ float g_bnsum2[C_];
// W^T split into bf16 hi/lo: [spec][n (64 padded)][k (4096)]
__device__ __nv_bfloat16 g_WT_hi[3][64 * HW];
__device__ __nv_bfloat16 g_WT_lo[3][64 * HW];
// Va2 (attn output) bf16 hi/lo, [row][64] (cols 50..63 stay zero)
__device__ __nv_bfloat16 g_Va2h[NROWS * 64];
__device__ __nv_bfloat16 g_Va2l[NROWS * 64];
// w_fc transposed+split: [n=4096][k=64] (k 50..63 zero)
__device__ __nv_bfloat16 g_WfcTh[HW * 64];
__device__ __nv_bfloat16 g_WfcTl[HW * 64];

// ---------------- helpers --------------------------------------------------
__device__ __forceinline__ uint32_t smem_u32(const void* p) {
    uint32_t a;
    asm("{ .reg .u64 t; cvta.to.shared.u64 t, %1; cvt.u32.u64 %0, t; }" : "=r"(a) : "l"(p));
    return a;
}
__device__ __forceinline__ void mma16816(float* c, const uint32_t* a, const uint32_t* b) {
    asm volatile("mma.sync.aligned.m16n8k16.row.col.f32.bf16.bf16.f32 "
        "{%0,%1,%2,%3}, {%4,%5,%6,%7}, {%8,%9}, {%0,%1,%2,%3};"
        : "+f"(c[0]), "+f"(c[1]), "+f"(c[2]), "+f"(c[3])
        : "r"(a[0]), "r"(a[1]), "r"(a[2]), "r"(a[3]), "r"(b[0]), "r"(b[1]));
}
__device__ __forceinline__ void ldm_x4(uint32_t* r, uint32_t addr) {
    asm volatile("ldmatrix.sync.aligned.m8n8.x4.shared.b16 {%0,%1,%2,%3}, [%4];"
        : "=r"(r[0]), "=r"(r[1]), "=r"(r[2]), "=r"(r[3]) : "r"(addr));
}
__device__ __forceinline__ void cpasync16(uint32_t dst, const void* src) {
    asm volatile("cp.async.cg.shared.global [%0], [%1], 16;" :: "r"(dst), "l"(src) : "memory");
}
#define CP_COMMIT() asm volatile("cp.async.commit_group;" ::: "memory")
#define CP_WAIT0()  asm volatile("cp.async.wait_group 0;" ::: "memory")

// ================= kernel 0: all weight prep + BN zero ====================
__global__ __launch_bounds__(256) void prep_all_kernel(
    const float* __restrict__ wq, const float* __restrict__ wk,
    const float* __restrict__ wv, const float* __restrict__ wfc)
{
    const int spec = blockIdx.y;
    if (spec < 3) {
        const float* W = (spec == 0) ? wq : (spec == 1) ? wk : wv;
        const int n = blockIdx.x;  // 0..63
        for (int kk = threadIdx.x; kk < HW; kk += 256) {
            float x = (n < PROJ) ? W[(size_t)kk * PROJ + n] : 0.f;
            __nv_bfloat16 h = __float2bfloat16(x);
            float lo = x - __bfloat162float(h);
            g_WT_hi[spec][n * HW + kk] = h;
            g_WT_lo[spec][n * HW + kk] = __float2bfloat16(lo);
        }
    } else {
        if (blockIdx.x == 0) {
            g_bnsum[threadIdx.x] = 0.f;
            g_bnsum2[threadIdx.x] = 0.f;
        }
        const int n0 = blockIdx.x * 64;
#pragma unroll 1
        for (int it = 0; it < 16; it++) {
            int idx = it * 256 + threadIdx.x;
            int kk = idx >> 6;
            int n  = n0 + (idx & 63);
            float x = (kk < PROJ) ? wfc[(size_t)kk * HW + n] : 0.f;
            __nv_bfloat16 h = __float2bfloat16(x);
            float lo = x - __bfloat162float(h);
            g_WfcTh[(size_t)n * 64 + kk] = h;
            g_WfcTl[(size_t)n * 64 + kk] = __float2bfloat16(lo);
        }
    }
}

// ================= kernel 1: proj, pipelined mma.sync bf16-split ==========
// Out[row, n] = sum_k A[row,k] * WT[n,k].  M-tile 64, N=64, K-chunk 64.
// Double-buffered smem; A prefetched to regs; B via cp.async.
#define PMT 64
#define PKC 64
#define PAD 72
#define NCHUNK (HW / PKC)
#define ASZ (PMT * PAD)
__global__ __launch_bounds__(128, 3) void proj_mma_kernel(
    const float* __restrict__ q, const float* __restrict__ k,
    const float* __restrict__ v)
{
    extern __shared__ __nv_bfloat16 sm[];
    __nv_bfloat16* AhB[2] = { sm,            sm + ASZ     };
    __nv_bfloat16* AlB[2] = { sm + 2 * ASZ,  sm + 3 * ASZ };
    __nv_bfloat16* BhB[2] = { sm + 4 * ASZ,  sm + 5 * ASZ };
    __nv_bfloat16* BlB[2] = { sm + 6 * ASZ,  sm + 7 * ASZ };

    const int spec = blockIdx.y;
    const float* A = (spec == 0) ? q : (spec == 1) ? k : v;
    const __nv_bfloat16* WTh = g_WT_hi[spec];
    const __nv_bfloat16* WTl = g_WT_lo[spec];
    float* Out = (spec == 0) ? g_Pq : (spec == 1) ? g_Pk : g_Pv;

    const int row0 = blockIdx.x * PMT;
    const int tid  = threadIdx.x;
    const int wid  = tid >> 5, lane = tid & 31;
    const int gr = lane >> 2, tq = lane & 3;

    // A load geometry: thread covers rows a+8j (j=0..7), cols b*4..b*4+3
    const int ar = tid >> 4, ab = tid & 15;
    const float* Abase = A + (size_t)(row0 + ar) * HW + ab * 4;
    const uint32_t aoff = (uint32_t)(ar * PAD + ab * 4) * 2;  // bytes
    const uint32_t sAh0 = smem_u32(AhB[0]), sAl0 = smem_u32(AlB[0]);

    // B cp.async geometry: thread covers n = bn+16j, k8 cols
    const int bn = tid >> 3, bk8 = (tid & 7) * 8;
    const uint32_t sBh0 = smem_u32(BhB[0]), sBl0 = smem_u32(BlB[0]);

    // ldmatrix source addresses
    const int a_row = wid * 16 + (lane & 15);
    const int a_k   = (lane >> 4) << 3;
    const uint32_t lAh = smem_u32(&AhB[0][a_row * PAD + a_k]);
    const uint32_t lAl = smem_u32(&AlB[0][a_row * PAD + a_k]);
    const int b_n = ((lane >> 4) << 3) + (lane & 7);
    const int b_k = ((lane >> 3) & 1) << 3;
    const uint32_t lBh = smem_u32(&BhB[0][b_n * PAD + b_k]);
    const uint32_t lBl = smem_u32(&BlB[0][b_n * PAD + b_k]);
    const uint32_t BUFB = ASZ * 2;  // byte offset between buffers

    float acc[8][4];
#pragma unroll
    for (int nt = 0; nt < 8; nt++)
#pragma unroll
        for (int i = 0; i < 4; i++) acc[nt][i] = 0.f;

    // ---- prologue: A[0] -> regs, B[0] -> smem buf0 via cp.async ----
    float4 apref[8];
#pragma unroll
    for (int j = 0; j < 8; j++)
        apref[j] = *(const float4*)(Abase + (size_t)j * 8 * HW);
#pragma unroll
    for (int j = 0; j < 4; j++) {
        int n = bn + 16 * j;
        uint32_t d = (uint32_t)(n * PAD + bk8) * 2;
        cpasync16(sBh0 + d, WTh + (size_t)n * HW + bk8);
        cpasync16(sBl0 + d, WTl + (size_t)n * HW + bk8);
    }
    CP_COMMIT();

    for (int kc = 0; kc < NCHUNK; kc++) {
        const uint32_t bsel = (kc & 1) ? BUFB : 0;
        // ---- convert prefetched A -> smem[buf] ----
#pragma unroll
        for (int j = 0; j < 8; j++) {
            float4 x = apref[j];
            uint32_t ux = __float_as_uint(x.x), uy = __float_as_uint(x.y);
            uint32_t uz = __float_as_uint(x.z), uw = __float_as_uint(x.w);
            uint32_t hi01 = __byte_perm(ux, uy, 0x7632);
            uint32_t hi23 = __byte_perm(uz, uw, 0x7632);
            float l0 = x.x - __uint_as_float(ux & 0xFFFF0000u);
            float l1 = x.y - __uint_as_float(uy & 0xFFFF0000u);
            float l2 = x.z - __uint_as_float(uz & 0xFFFF0000u);
            float l3 = x.w - __uint_as_float(uw & 0xFFFF0000u);
            __nv_bfloat162 lo01 = __float22bfloat162_rn(make_float2(l0, l1));
            __nv_bfloat162 lo23 = __float22bfloat162_rn(make_float2(l2, l3));
            uint32_t d = aoff + j * (8 * PAD * 2);
            asm volatile("st.shared.v2.b32 [%0], {%1, %2};"
                :: "r"(sAh0 + bsel + d), "r"(hi01), "r"(hi23) : "memory");
            asm volatile("st.shared.v2.b32 [%0], {%1, %2};"
                :: "r"(sAl0 + bsel + d), "r"(*(uint32_t*)&lo01), "r"(*(uint32_t*)&lo23) : "memory");
        }
        // ---- prefetch next A chunk into regs (overlaps mma below) ----
        if (kc + 1 < NCHUNK) {
            const float* An = Abase + (kc + 1) * PKC;
#pragma unroll
            for (int j = 0; j < 8; j++)
                apref[j] = *(const float4*)(An + (size_t)j * 8 * HW);
        }
        CP_WAIT0();            // B[kc] arrived (own group)
        __syncthreads();       // A stores + everyone's B visible
        // ---- issue B[kc+1] into other buffer ----
        if (kc + 1 < NCHUNK) {
            const uint32_t obsel = bsel ^ BUFB;
            const int k0n = (kc + 1) * PKC;
#pragma unroll
            for (int j = 0; j < 4; j++) {
                int n = bn + 16 * j;
                uint32_t d = (uint32_t)(n * PAD + bk8) * 2;
                cpasync16(sBh0 + obsel + d, WTh + (size_t)n * HW + k0n + bk8);
                cpasync16(sBl0 + obsel + d, WTl + (size_t)n * HW + k0n + bk8);
            }
            CP_COMMIT();
        }
        // ---- mma on buf ----
#pragma unroll
        for (int ksi = 0; ksi < 4; ksi++) {
            const uint32_t koff = bsel + ksi * 32;
            uint32_t ah[4], al[4];
            ldm_x4(ah, lAh + koff);
            ldm_x4(al, lAl + koff);
#pragma unroll
            for (int g = 0; g < 4; g++) {
                uint32_t bh4[4], bl4[4];
                const uint32_t boff = g * 16 * (PAD * 2) + koff;
                ldm_x4(bh4, lBh + boff);
                ldm_x4(bl4, lBl + boff);
                mma16816(acc[2 * g],     ah, bh4);
                mma16816(acc[2 * g],     ah, bl4);
                mma16816(acc[2 * g],     al, bh4);
                mma16816(acc[2 * g + 1], ah, bh4 + 2);
                mma16816(acc[2 * g + 1], ah, bl4 + 2);
                mma16816(acc[2 * g + 1], al, bh4 + 2);
            }
        }
    }

    // ---- epilogue ----
    const int r0 = row0 + wid * 16 + gr;
#pragma unroll
    for (int nt = 0; nt < 8; nt++) {
        int col = nt * 8 + tq * 2;
        if (col < PROJ) {
            Out[(size_t)r0 * PROJ + col]           = acc[nt][0];
            Out[(size_t)r0 * PROJ + col + 1]       = acc[nt][1];
            Out[(size_t)(r0 + 8) * PROJ + col]     = acc[nt][2];
            Out[(size_t)(r0 + 8) * PROJ + col + 1] = acc[nt][3];
        }
    }
}

// ================= kernel 2: 5x5 attention + inner residual ===============
__global__ __launch_bounds__(256) void attn_kernel() {
    const int b = blockIdx.x, tid = threadIdx.x;
    __shared__ float logit_s[NH * NH];
    __shared__ float attn_s[NH * NH];
    if (tid < NH * NH) logit_s[tid] = 0.f;
    __syncthreads();

    const size_t row = (size_t)(b * C_ + tid);
    const size_t rp = row * PROJ;

    float q50[PROJ], k50[PROJ];
#pragma unroll
    for (int t = 0; t < PROJ; t++) { q50[t] = g_Pq[rp + t]; k50[t] = g_Pk[rp + t]; }

#pragma unroll
    for (int i = 0; i < NH; i++)
#pragma unroll
        for (int j = 0; j < NH; j++) {
            float s = 0.f;
#pragma unroll
            for (int l = 0; l < LD; l++) s += q50[i * LD + l] * k50[j * LD + l];
            s += __shfl_xor_sync(~0u, s, 16);
            s += __shfl_xor_sync(~0u, s, 8);
            s += __shfl_xor_sync(~0u, s, 4);
            s += __shfl_xor_sync(~0u, s, 2);
            s += __shfl_xor_sync(~0u, s, 1);
            if ((tid & 31) == 0) atomicAdd(&logit_s[i * NH + j], s);
        }
    __syncthreads();

    if (tid == 0) {
        const float inv = rsqrtf((float)(C_ * LD));
        for (int i = 0; i < NH; i++) {
            float m = -1e30f;
            for (int j = 0; j < NH; j++) m = fmaxf(m, logit_s[i * NH + j] * inv);
            float e[NH], se = 0.f;
            for (int j = 0; j < NH; j++) { e[j] = expf(logit_s[i * NH + j] * inv - m); se += e[j]; }
            float rinv = 1.0f / se;
            for (int j = 0; j < NH; j++) attn_s[i * NH + j] = e[j] * rinv;
        }
    }
    __syncthreads();

    float v50[PROJ];
#pragma unroll
    for (int t = 0; t < PROJ; t++) v50[t] = g_Pv[rp + t];
#pragma unroll
    for (int i = 0; i < NH; i++) {
        float a0 = attn_s[i * NH + 0], a1 = attn_s[i * NH + 1], a2 = attn_s[i * NH + 2],
              a3 = attn_s[i * NH + 3], a4 = attn_s[i * NH + 4];
#pragma unroll
        for (int l = 0; l < LD; l++) {
            float s = v50[i * LD + l]
                + a0 * v50[l] + a1 * v50[LD + l] + a2 * v50[2 * LD + l]
                + a3 * v50[3 * LD + l] + a4 * v50[4 * LD + l];
            __nv_bfloat16 h = __float2bfloat16(s);
            float lo = s - __bfloat162float(h);
            g_Va2h[row * 64 + i * LD + l] = h;
            g_Va2l[row * 64 + i * LD + l] = __float2bfloat16(lo);
        }
    }
}

// ================= kernel 3: fc via mma.sync + residual + BN stats ========
#define FMT 128
#define FNT 128
__global__ __launch_bounds__(256) void fc_mma_kernel(
    const float* __restrict__ v, float* __restrict__ out)
{
    extern __shared__ char fsm[];
    __nv_bfloat16* Ah = (__nv_bfloat16*)fsm;            // [128][72]
    __nv_bfloat16* Al = Ah + FMT * PAD;
    __nv_bfloat16* Bh = Al + FMT * PAD;                 // [128][72]
    __nv_bfloat16* Bl = Bh + FNT * PAD;

    const int n0   = blockIdx.x * FNT;
    const int row0 = blockIdx.y * FMT;
    const int tid  = threadIdx.x;
    const int wid  = tid >> 5, lane = tid & 31;
    const int gr = lane >> 2, tq = lane & 3;

#pragma unroll
    for (int j = 0; j < 4; j++) {
        int i = tid + j * 256;
        int r = i >> 3, k8 = (i & 7) * 8;
        *(uint4*)&Ah[r * PAD + k8] = *(const uint4*)&g_Va2h[(size_t)(row0 + r) * 64 + k8];
        *(uint4*)&Al[r * PAD + k8] = *(const uint4*)&g_Va2l[(size_t)(row0 + r) * 64 + k8];
        *(uint4*)&Bh[r * PAD + k8] = *(const uint4*)&g_WfcTh[(size_t)(n0 + r) * 64 + k8];
        *(uint4*)&Bl[r * PAD + k8] = *(const uint4*)&g_WfcTl[(size_t)(n0 + r) * 64 + k8];
    }
    __syncthreads();

    const int a_row = wid * 16 + (lane & 15);
    const int a_k   = (lane >> 4) << 3;
    const uint32_t sAh = smem_u32(&Ah[a_row * PAD + a_k]);
    const uint32_t sAl = smem_u32(&Al[a_row * PAD + a_k]);
    const int b_n = ((lane >> 4) << 3) + (lane & 7);
    const int b_k = ((lane >> 3) & 1) << 3;
    const uint32_t sBh = smem_u32(&Bh[b_n * PAD + b_k]);
    const uint32_t sBl = smem_u32(&Bl[b_n * PAD + b_k]);

    float acc[16][4];
#pragma unroll
    for (int nt = 0; nt < 16; nt++)
#pragma unroll
        for (int i = 0; i < 4; i++) acc[nt][i] = 0.f;

#pragma unroll
    for (int ksi = 0; ksi < 4; ksi++) {
        const uint32_t koff = ksi * 32;
        uint32_t ah[4], al[4];
        ldm_x4(ah, sAh + koff);
        ldm_x4(al, sAl + koff);
#pragma unroll
        for (int g = 0; g < 8; g++) {
            uint32_t bh4[4], bl4[4];
            const uint32_t boff = g * 16 * (PAD * 2) + koff;
            ldm_x4(bh4, sBh + boff);
            ldm_x4(bl4, sBl + boff);
            mma16816(acc[2 * g],     ah, bh4);
            mma16816(acc[2 * g],     ah, bl4);
            mma16816(acc[2 * g],     al, bh4);
            mma16816(acc[2 * g + 1], ah, bh4 + 2);
            mma16816(acc[2 * g + 1], ah, bl4 + 2);
            mma16816(acc[2 * g + 1], al, bh4 + 2);
        }
    }

    const int r0 = row0 + wid * 16 + gr;
    const int r1 = r0 + 8;
    float s0 = 0.f, s20 = 0.f, s1 = 0.f, s21 = 0.f;
#pragma unroll
    for (int nt = 0; nt < 16; nt++) {
        int col = n0 + nt * 8 + tq * 2;
        float2 v0 = *(const float2*)(v + (size_t)r0 * HW + col);
        float2 v1 = *(const float2*)(v + (size_t)r1 * HW + col);
        float o00 = v0.x + acc[nt][0], o01 = v0.y + acc[nt][1];
        float o10 = v1.x + acc[nt][2], o11 = v1.y + acc[nt][3];
        *(float2*)(out + (size_t)r0 * HW + col) = make_float2(o00, o01);
        *(float2*)(out + (size_t)r1 * HW + col) = make_float2(o10, o11);
        s0  += o00 + o01;        s1  += o10 + o11;
        s20 += o00 * o00 + o01 * o01;
        s21 += o10 * o10 + o11 * o11;
    }
    s0  += __shfl_xor_sync(~0u, s0, 1);  s0  += __shfl_xor_sync(~0u, s0, 2);
    s1  += __shfl_xor_sync(~0u, s1, 1);  s1  += __shfl_xor_sync(~0u, s1, 2);
    s20 += __shfl_xor_sync(~0u, s20, 1); s20 += __shfl_xor_sync(~0u, s20, 2);
    s21 += __shfl_xor_sync(~0u, s21, 1); s21 += __shfl_xor_sync(~0u, s21, 2);
    if (tq == 0) {
        atomicAdd(&g_bnsum[r0 & (C_ - 1)], s0);
        atomicAdd(&g_bnsum2[r0 & (C_ - 1)], s20);
        atomicAdd(&g_bnsum[r1 & (C_ - 1)], s1);
        atomicAdd(&g_bnsum2[r1 & (C_ - 1)], s21);
    }
}

// ================= kernel 4: finalize BN scale/shift ======================
__global__ void finalize_kernel(const float* __restrict__ gamma,
                                const float* __restrict__ beta) {
    int ch = threadIdx.x;
    if (ch < C_) {
        const float n = (float)(B_ * HW);
        float mean = g_bnsum[ch] / n;
        float var  = g_bnsum2[ch] / n - mean * mean;
        float sc = gamma[ch] * rsqrtf(var + 1e-5f);
        g_scale[ch] = sc;
        g_shift[ch] = beta[ch] - mean * sc;
    }
}

// ================= kernel 5: apply BN =====================================
__global__ __launch_bounds__(256) void bn_apply_kernel(float* __restrict__ out) {
    size_t idx4 = (size_t)blockIdx.x * 256 + threadIdx.x;
    size_t i = idx4 * 4;
    int ch = (int)((i >> 12) & (C_ - 1));
    float sc = g_scale[ch], sh = g_shift[ch];
    float4 x = *(float4*)(out + i);
    x.x = x.x * sc + sh; x.y = x.y * sc + sh;
    x.z = x.z * sc + sh; x.w = x.w * sc + sh;
    *(float4*)(out + i) = x;
}

extern "C" void kernel_launch(void* const* d_in, const int* in_sizes, int n_in,
                              void* d_out, int out_size) {
    const float* q     = (const float*)d_in[0];
    const float* k     = (const float*)d_in[1];
    const float* v     = (const float*)d_in[2];
    const float* w_q   = (const float*)d_in[3];
    const float* w_k   = (const float*)d_in[4];
    const float* w_v   = (const float*)d_in[5];
    const float* w_fc  = (const float*)d_in[6];
    const float* gamma = (const float*)d_in[7];
    const float* beta  = (const float*)d_in[8];
    float* out = (float*)d_out;

    const int PROJ_SMEM = 8 * ASZ * 2;       // 73728 bytes
    const int FC_SMEM   = 4 * FMT * PAD * 2; // 73728 bytes
    cudaFuncSetAttribute(proj_mma_kernel,
                         cudaFuncAttributeMaxDynamicSharedMemorySize, PROJ_SMEM);
    cudaFuncSetAttribute(fc_mma_kernel,
                         cudaFuncAttributeMaxDynamicSharedMemorySize, FC_SMEM);

    prep_all_kernel<<<dim3(64, 4), 256>>>(w_q, w_k, w_v, w_fc);
    proj_mma_kernel<<<dim3(NROWS / PMT, 3), 128, PROJ_SMEM>>>(q, k, v);
    attn_kernel<<<B_, 256>>>();
    fc_mma_kernel<<<dim3(HW / FNT, NROWS / FMT), 256, FC_SMEM>>>(v, out);
    finalize_kernel<<<1, 256>>>(gamma, beta);
    bn_apply_kernel<<<(NROWS * HW) / (256 * 4), 256>>>(out);
}